// round 3
// baseline (speedup 1.0000x reference)
#include <cuda_runtime.h>
#include <math.h>

// ---------------- problem constants ----------------
#define NTOK 8192      // BATCH*SEQ tokens
#define HDIM 1024
#define IDIM 2048
#define NEXP 8
#define NSLOT (NTOK*2) // 16384 (token, expert) assignments

// ---------------- GEMM tiling ----------------
#define BM 128
#define BN 128
#define BK 16
#define MAXT 136       // max row tiles: 16384/128 + 8 experts partial

// ---------------- device scratch (static, no allocs) ----------------
__device__ float g_H1[(size_t)NSLOT * IDIM];   // 128 MB  gelu(X @ Wfc^T) per slot-row
__device__ float g_Y2[(size_t)NSLOT * HDIM];   // 64 MB   H1 @ Wproj^T per slot-row
__device__ int   g_perm[NSLOT];                // slot-row -> token
__device__ float g_wt[NSLOT];                  // slot-row -> routing weight
__device__ int   g_slot[NSLOT];                // token*2+k -> slot-row (inverse map)
__device__ int   g_te[NSLOT];                  // token*2+k -> expert
__device__ float g_twt[NSLOT];                 // token*2+k -> weight
__device__ int   g_counts[NEXP];
__device__ int   g_offsets[NEXP];
__device__ int   g_cursors[NEXP];
__device__ int   g_numTiles;
__device__ int   g_tileE[MAXT];
__device__ int   g_tileRow0[MAXT];
__device__ int   g_tileRows[MAXT];

// ---------------- init ----------------
__global__ void k_init() {
    int i = threadIdx.x;
    if (i < NEXP) { g_counts[i] = 0; g_cursors[i] = 0; }
}

// ---------------- router: warp per token ----------------
__global__ void k_router(const float* __restrict__ X, const float* __restrict__ Wg,
                         float* __restrict__ logits, int write_logits) {
    int warp = threadIdx.x >> 5;
    int lane = threadIdx.x & 31;
    int t = blockIdx.x * (blockDim.x >> 5) + warp;
    if (t >= NTOK) return;
    const float* xp = X + (size_t)t * HDIM;
    float acc[NEXP];
#pragma unroll
    for (int e = 0; e < NEXP; e++) acc[e] = 0.f;
    for (int k = lane; k < HDIM; k += 32) {
        float xv = __ldg(xp + k);
#pragma unroll
        for (int e = 0; e < NEXP; e++) acc[e] = fmaf(xv, __ldg(Wg + e * HDIM + k), acc[e]);
    }
#pragma unroll
    for (int e = 0; e < NEXP; e++) {
        acc[e] += __shfl_xor_sync(0xffffffffu, acc[e], 16);
        acc[e] += __shfl_xor_sync(0xffffffffu, acc[e], 8);
        acc[e] += __shfl_xor_sync(0xffffffffu, acc[e], 4);
        acc[e] += __shfl_xor_sync(0xffffffffu, acc[e], 2);
        acc[e] += __shfl_xor_sync(0xffffffffu, acc[e], 1);
    }
    if (lane == 0) {
        if (write_logits) {
#pragma unroll
            for (int e = 0; e < NEXP; e++) logits[(size_t)t * NEXP + e] = acc[e];
        }
        // top-2 (first-occurrence tie-break, matches jax top_k)
        int i0 = 0;
#pragma unroll
        for (int e = 1; e < NEXP; e++) if (acc[e] > acc[i0]) i0 = e;
        int i1 = (i0 == 0) ? 1 : 0;
#pragma unroll
        for (int e = 0; e < NEXP; e++) if (e != i1 && e != i0 && acc[e] > acc[i1]) i1 = e;
        // normalized top-2 weights: p0/(p0+p1) = 1/(1+exp(l1-l0))
        float d  = expf(acc[i1] - acc[i0]);
        float w0 = 1.f / (1.f + d);
        float w1 = 1.f - w0;
        g_te[2 * t]     = i0; g_twt[2 * t]     = w0;
        g_te[2 * t + 1] = i1; g_twt[2 * t + 1] = w1;
        atomicAdd(&g_counts[i0], 1);
        atomicAdd(&g_counts[i1], 1);
    }
}

// ---------------- scan + tile schedule (tiny, 1 thread) ----------------
__global__ void k_scan() {
    int off = 0, t = 0;
    for (int e = 0; e < NEXP; e++) {
        g_offsets[e] = off;
        int c = g_counts[e];
        for (int r = 0; r < c; r += BM) {
            g_tileE[t]    = e;
            g_tileRow0[t] = off + r;
            g_tileRows[t] = (c - r < BM) ? (c - r) : BM;
            t++;
        }
        off += c;
    }
    g_numTiles = t;
}

// ---------------- scatter tokens into per-expert rows ----------------
__global__ void k_scatter() {
    int t = blockIdx.x * blockDim.x + threadIdx.x;
    if (t >= NTOK) return;
#pragma unroll
    for (int s = 0; s < 2; s++) {
        int e = g_te[2 * t + s];
        int pos = g_offsets[e] + atomicAdd(&g_cursors[e], 1);
        g_perm[pos] = t;
        g_wt[pos]   = g_twt[2 * t + s];
        g_slot[2 * t + s] = pos;
    }
}

// ---------------- GEMM1: H1 = gelu(gather(X) @ Wfc[e]^T), K=1024 ----------------
__global__ __launch_bounds__(256) void k_gemm1(const float* __restrict__ X,
                                               const float* __restrict__ Wfc) {
    int tile = blockIdx.x;
    if (tile >= g_numTiles) return;
    int e = g_tileE[tile], row0 = g_tileRow0[tile], rows = g_tileRows[tile];
    int col0 = blockIdx.y * BN;

    __shared__ __align__(16) float As[BK][BM + 4];
    __shared__ __align__(16) float Bs[BK][BN + 4];
    __shared__ int rowTok[BM];

    int tid = threadIdx.x;
    int tx = tid & 15, ty = tid >> 4;
    const float* Bp = Wfc + (size_t)e * IDIM * HDIM + (size_t)col0 * HDIM;

    if (tid < BM) rowTok[tid] = (tid < rows) ? g_perm[row0 + tid] : -1;
    __syncthreads();

    float acc[8][8];
#pragma unroll
    for (int i = 0; i < 8; i++)
#pragma unroll
        for (int j = 0; j < 8; j++) acc[i][j] = 0.f;

    for (int k0 = 0; k0 < HDIM; k0 += BK) {
#pragma unroll
        for (int i = 0; i < 2; i++) {
            int idx = tid + i * 256;        // 0..511 -> 128 rows x 4 float4
            int m = idx >> 2, k4 = idx & 3;
            float4 v = make_float4(0.f, 0.f, 0.f, 0.f);
            int tok = rowTok[m];
            if (tok >= 0) v = *(const float4*)(X + (size_t)tok * HDIM + k0 + k4 * 4);
            As[k4 * 4 + 0][m] = v.x; As[k4 * 4 + 1][m] = v.y;
            As[k4 * 4 + 2][m] = v.z; As[k4 * 4 + 3][m] = v.w;
            float4 w = *(const float4*)(Bp + (size_t)m * HDIM + k0 + k4 * 4);
            Bs[k4 * 4 + 0][m] = w.x; Bs[k4 * 4 + 1][m] = w.y;
            Bs[k4 * 4 + 2][m] = w.z; Bs[k4 * 4 + 3][m] = w.w;
        }
        __syncthreads();
#pragma unroll
        for (int k = 0; k < BK; k++) {
            float a[8], b[8];
            *(float4*)&a[0] = *(const float4*)&As[k][ty * 8];
            *(float4*)&a[4] = *(const float4*)&As[k][ty * 8 + 4];
            *(float4*)&b[0] = *(const float4*)&Bs[k][tx * 8];
            *(float4*)&b[4] = *(const float4*)&Bs[k][tx * 8 + 4];
#pragma unroll
            for (int i = 0; i < 8; i++)
#pragma unroll
                for (int j = 0; j < 8; j++) acc[i][j] = fmaf(a[i], b[j], acc[i][j]);
        }
        __syncthreads();
    }
#pragma unroll
    for (int i = 0; i < 8; i++) {
        int m = ty * 8 + i;
        if (m < rows) {
            float* op = g_H1 + (size_t)(row0 + m) * IDIM + col0 + tx * 8;
#pragma unroll
            for (int j = 0; j < 8; j++) {
                float v = acc[i][j];
                op[j] = 0.5f * v * (1.f + erff(v * 0.70710678118654752f)); // exact gelu
            }
        }
    }
}

// ---------------- GEMM2: Y2 = H1 @ Wproj[e]^T, K=2048 ----------------
__global__ __launch_bounds__(256) void k_gemm2(const float* __restrict__ Wproj) {
    int tile = blockIdx.x;
    if (tile >= g_numTiles) return;
    int e = g_tileE[tile], row0 = g_tileRow0[tile], rows = g_tileRows[tile];
    int col0 = blockIdx.y * BN;

    __shared__ __align__(16) float As[BK][BM + 4];
    __shared__ __align__(16) float Bs[BK][BN + 4];

    int tid = threadIdx.x;
    int tx = tid & 15, ty = tid >> 4;
    const float* Ap = g_H1 + (size_t)row0 * IDIM;
    const float* Bp = Wproj + (size_t)e * HDIM * IDIM + (size_t)col0 * IDIM;

    float acc[8][8];
#pragma unroll
    for (int i = 0; i < 8; i++)
#pragma unroll
        for (int j = 0; j < 8; j++) acc[i][j] = 0.f;

    for (int k0 = 0; k0 < IDIM; k0 += BK) {
#pragma unroll
        for (int i = 0; i < 2; i++) {
            int idx = tid + i * 256;
            int m = idx >> 2, k4 = idx & 3;
            float4 v = make_float4(0.f, 0.f, 0.f, 0.f);
            if (m < rows) v = *(const float4*)(Ap + (size_t)m * IDIM + k0 + k4 * 4);
            As[k4 * 4 + 0][m] = v.x; As[k4 * 4 + 1][m] = v.y;
            As[k4 * 4 + 2][m] = v.z; As[k4 * 4 + 3][m] = v.w;
            float4 w = *(const float4*)(Bp + (size_t)m * IDIM + k0 + k4 * 4);
            Bs[k4 * 4 + 0][m] = w.x; Bs[k4 * 4 + 1][m] = w.y;
            Bs[k4 * 4 + 2][m] = w.z; Bs[k4 * 4 + 3][m] = w.w;
        }
        __syncthreads();
#pragma unroll
        for (int k = 0; k < BK; k++) {
            float a[8], b[8];
            *(float4*)&a[0] = *(const float4*)&As[k][ty * 8];
            *(float4*)&a[4] = *(const float4*)&As[k][ty * 8 + 4];
            *(float4*)&b[0] = *(const float4*)&Bs[k][tx * 8];
            *(float4*)&b[4] = *(const float4*)&Bs[k][tx * 8 + 4];
#pragma unroll
            for (int i = 0; i < 8; i++)
#pragma unroll
                for (int j = 0; j < 8; j++) acc[i][j] = fmaf(a[i], b[j], acc[i][j]);
        }
        __syncthreads();
    }
#pragma unroll
    for (int i = 0; i < 8; i++) {
        int m = ty * 8 + i;
        if (m < rows) {
            float* op = g_Y2 + (size_t)(row0 + m) * HDIM + col0 + tx * 8;
#pragma unroll
            for (int j = 0; j < 8; j++) op[j] = acc[i][j];
        }
    }
}

// ---------------- combine: out[t] = w0*Y2[slot0] + w1*Y2[slot1] ----------------
__global__ void k_combine(float* __restrict__ out) {
    int i4 = blockIdx.x * blockDim.x + threadIdx.x;   // over NTOK*HDIM/4
    if (i4 >= NTOK * (HDIM / 4)) return;
    int t  = i4 / (HDIM / 4);
    int h4 = i4 % (HDIM / 4);
    int p0 = g_slot[2 * t], p1 = g_slot[2 * t + 1];
    float w0 = g_wt[p0], w1 = g_wt[p1];
    float4 a = *(const float4*)(g_Y2 + (size_t)p0 * HDIM + h4 * 4);
    float4 b = *(const float4*)(g_Y2 + (size_t)p1 * HDIM + h4 * 4);
    float4 o;
    o.x = fmaf(w0, a.x, w1 * b.x);
    o.y = fmaf(w0, a.y, w1 * b.y);
    o.z = fmaf(w0, a.z, w1 * b.z);
    o.w = fmaf(w0, a.w, w1 * b.w);
    *((float4*)out + i4) = o;
}

// ---------------- launch ----------------
extern "C" void kernel_launch(void* const* d_in, const int* in_sizes, int n_in,
                              void* d_out, int out_size) {
    const float* X     = (const float*)d_in[0];   // [2,4096,1024]
    const float* Wg    = (const float*)d_in[1];   // [8,1024]
    const float* Wfc   = (const float*)d_in[2];   // [8,2048,1024]
    const float* Wproj = (const float*)d_in[3];   // [8,1024,2048]
    float* out = (float*)d_out;

    int write_logits = (out_size >= NTOK * HDIM + NTOK * NEXP) ? 1 : 0;
    float* logits = out + (size_t)NTOK * HDIM;

    k_init<<<1, 32>>>();
    k_router<<<NTOK / 8, 256>>>(X, Wg, logits, write_logits);
    k_scan<<<1, 1>>>();
    k_scatter<<<NTOK / 256, 256>>>();
    k_gemm1<<<dim3(MAXT, IDIM / BN), 256>>>(X, Wfc);
    k_gemm2<<<dim3(MAXT, HDIM / BN), 256>>>(Wproj);
    k_combine<<<(NTOK * (HDIM / 4) + 255) / 256, 256>>>(out);
}